// round 1
// baseline (speedup 1.0000x reference)
#include <cuda_runtime.h>
#include <math.h>

// Problem constants
constexpr int Bc = 4;
constexpr int Sc = 2048;
constexpr int Dc = 1024;
constexpr int Hc = 16;
constexpr int DHc = 64;        // head dim
constexpr int Mc = Bc * Sc;    // 8192 rows

// Scratch (device globals — no allocation allowed)
__device__ __align__(16) float g_q[(size_t)Bc * Hc * Sc * DHc];
__device__ __align__(16) float g_k[(size_t)Bc * Hc * Sc * DHc];
__device__ __align__(16) float g_v[(size_t)Bc * Hc * Sc * DHc];
__device__ __align__(16) float g_ctx[(size_t)Mc * Dc];

// ---------------------------------------------------------------------------
// GEMM + bias: out = (X @ W + b) * scale
//   X: [M, K=1024] row-major, W: [K=1024, N=1024] row-major
//   headmode=1: write to head-major layout [B, H, S, Dh]
//   headmode=0: write plain [M, N]
// Tiles: 64x64x16, 256 threads, 4x4 per-thread micro-tile.
// ---------------------------------------------------------------------------
__global__ __launch_bounds__(256) void gemm_bias(
    const float* __restrict__ X,
    const float* __restrict__ W,
    const float* __restrict__ bias,
    float* __restrict__ out,
    float scale, int headmode)
{
    __shared__ float As[16][64];   // [k][m]
    __shared__ float Bs[16][64];   // [k][n]

    const int m0 = blockIdx.y * 64;
    const int n0 = blockIdx.x * 64;
    const int tid = threadIdx.x;
    const int tx = tid & 15;       // 0..15 -> n
    const int ty = tid >> 4;       // 0..15 -> m

    float acc[4][4] = {};

    const int mlA = tid >> 2;           // 0..63
    const int klA = (tid & 3) * 4;      // 0,4,8,12
    const int klB = tid >> 4;           // 0..15
    const int nlB = (tid & 15) * 4;     // 0..60

    for (int k0 = 0; k0 < Dc; k0 += 16) {
        float4 a = *(const float4*)(X + (size_t)(m0 + mlA) * Dc + k0 + klA);
        float4 b = *(const float4*)(W + (size_t)(k0 + klB) * Dc + n0 + nlB);
        As[klA + 0][mlA] = a.x;
        As[klA + 1][mlA] = a.y;
        As[klA + 2][mlA] = a.z;
        As[klA + 3][mlA] = a.w;
        *(float4*)&Bs[klB][nlB] = b;
        __syncthreads();

        #pragma unroll
        for (int kk = 0; kk < 16; ++kk) {
            float4 av = *(float4*)&As[kk][ty * 4];
            float4 bv = *(float4*)&Bs[kk][tx * 4];
            acc[0][0] += av.x * bv.x; acc[0][1] += av.x * bv.y;
            acc[0][2] += av.x * bv.z; acc[0][3] += av.x * bv.w;
            acc[1][0] += av.y * bv.x; acc[1][1] += av.y * bv.y;
            acc[1][2] += av.y * bv.z; acc[1][3] += av.y * bv.w;
            acc[2][0] += av.z * bv.x; acc[2][1] += av.z * bv.y;
            acc[2][2] += av.z * bv.z; acc[2][3] += av.z * bv.w;
            acc[3][0] += av.w * bv.x; acc[3][1] += av.w * bv.y;
            acc[3][2] += av.w * bv.z; acc[3][3] += av.w * bv.w;
        }
        __syncthreads();
    }

    const int n = n0 + tx * 4;
    const float4 bv = *(const float4*)(bias + n);

    #pragma unroll
    for (int i = 0; i < 4; ++i) {
        const int m = m0 + ty * 4 + i;
        float4 o;
        o.x = (acc[i][0] + bv.x) * scale;
        o.y = (acc[i][1] + bv.y) * scale;
        o.z = (acc[i][2] + bv.z) * scale;
        o.w = (acc[i][3] + bv.w) * scale;
        if (headmode) {
            const int bb = m >> 11;        // m / 2048
            const int ss = m & 2047;
            const int h  = n >> 6;         // n / 64
            const int d  = n & 63;
            const size_t idx = ((size_t)(bb * Hc + h) * Sc + ss) * DHc + d;
            *(float4*)(out + idx) = o;
        } else {
            *(float4*)(out + (size_t)m * Dc + n) = o;
        }
    }
}

// ---------------------------------------------------------------------------
// Flash attention (fp32, online softmax).
//   Q pre-scaled by 1/sqrt(Dh) at projection time.
//   Grid: (S/64, B*H). Block: 256 threads (16x16).
//   BM=64 query rows per CTA, BN=32 keys per tile, Dh=64.
// ---------------------------------------------------------------------------
__global__ __launch_bounds__(256) void flash_attn()
{
    __shared__ float Qs[64][68];
    __shared__ float Ks[32][68];
    __shared__ float Vs[32][68];
    __shared__ float Ps[64][32];

    const int qt = blockIdx.x;        // 0..31
    const int bh = blockIdx.y;        // 0..63
    const float* Q = g_q + (size_t)bh * Sc * DHc;
    const float* K = g_k + (size_t)bh * Sc * DHc;
    const float* V = g_v + (size_t)bh * Sc * DHc;

    const int tid = threadIdx.x;
    const int tx = tid & 15;          // key-col / out-dim group
    const int ty = tid >> 4;          // query-row group
    const int r0 = ty * 4;

    // Load Q tile (64 x 64): 1024 float4, 4 per thread
    #pragma unroll
    for (int i = tid; i < 64 * 16; i += 256) {
        const int r = i >> 4;
        const int c4 = (i & 15) * 4;
        *(float4*)&Qs[r][c4] = *(const float4*)(Q + (size_t)(qt * 64 + r) * DHc + c4);
    }

    float mi[4], li[4], acc[4][4];
    #pragma unroll
    for (int i = 0; i < 4; ++i) {
        mi[i] = -1e30f;
        li[i] = 0.0f;
        #pragma unroll
        for (int j = 0; j < 4; ++j) acc[i][j] = 0.0f;
    }

    const int c0 = tx * 2;   // two key columns per thread
    const int d0 = tx * 4;   // four output dims per thread

    for (int t = 0; t < Sc / 32; ++t) {
        __syncthreads();   // protects Ks/Vs (and Qs visibility on t=0)

        // Load K,V tiles (32 x 64 each): 512 float4 each, 2 per thread
        #pragma unroll
        for (int i = tid; i < 32 * 16; i += 256) {
            const int r = i >> 4;
            const int c4 = (i & 15) * 4;
            *(float4*)&Ks[r][c4] = *(const float4*)(K + (size_t)(t * 32 + r) * DHc + c4);
            *(float4*)&Vs[r][c4] = *(const float4*)(V + (size_t)(t * 32 + r) * DHc + c4);
        }
        __syncthreads();

        // S = Q K^T  (Q pre-scaled): 4 rows x 2 cols per thread
        float sv[4][2] = {};
        #pragma unroll
        for (int k = 0; k < DHc; k += 4) {
            const float4 k0v = *(float4*)&Ks[c0][k];
            const float4 k1v = *(float4*)&Ks[c0 + 1][k];
            #pragma unroll
            for (int i = 0; i < 4; ++i) {
                const float4 qv = *(float4*)&Qs[r0 + i][k];
                sv[i][0] += qv.x * k0v.x + qv.y * k0v.y + qv.z * k0v.z + qv.w * k0v.w;
                sv[i][1] += qv.x * k1v.x + qv.y * k1v.y + qv.z * k1v.z + qv.w * k1v.w;
            }
        }

        // Online softmax per row (row spread over 16 lanes, width-16 shuffles)
        #pragma unroll
        for (int i = 0; i < 4; ++i) {
            float mx = fmaxf(sv[i][0], sv[i][1]);
            #pragma unroll
            for (int off = 8; off > 0; off >>= 1)
                mx = fmaxf(mx, __shfl_xor_sync(0xffffffffu, mx, off, 16));
            const float mnew = fmaxf(mi[i], mx);
            const float corr = __expf(mi[i] - mnew);
            mi[i] = mnew;
            const float p0 = __expf(sv[i][0] - mnew);
            const float p1 = __expf(sv[i][1] - mnew);
            Ps[r0 + i][c0] = p0;
            Ps[r0 + i][c0 + 1] = p1;
            float ls = p0 + p1;
            #pragma unroll
            for (int off = 8; off > 0; off >>= 1)
                ls += __shfl_xor_sync(0xffffffffu, ls, off, 16);
            li[i] = li[i] * corr + ls;
            #pragma unroll
            for (int j = 0; j < 4; ++j) acc[i][j] *= corr;
        }
        __syncthreads();   // Ps ready for all

        // O += P @ V : each thread accumulates 4 rows x 4 dims
        #pragma unroll
        for (int c = 0; c < 32; ++c) {
            const float4 v4 = *(float4*)&Vs[c][d0];
            #pragma unroll
            for (int i = 0; i < 4; ++i) {
                const float p = Ps[r0 + i][c];
                acc[i][0] += p * v4.x;
                acc[i][1] += p * v4.y;
                acc[i][2] += p * v4.z;
                acc[i][3] += p * v4.w;
            }
        }
    }

    // Epilogue: normalize and write ctx in [B, S, D] layout
    const int bb = bh >> 4;
    const int h = bh & 15;
    #pragma unroll
    for (int i = 0; i < 4; ++i) {
        const int s_idx = qt * 64 + r0 + i;
        const float inv = 1.0f / li[i];
        float4 o;
        o.x = acc[i][0] * inv;
        o.y = acc[i][1] * inv;
        o.z = acc[i][2] * inv;
        o.w = acc[i][3] * inv;
        *(float4*)(g_ctx + ((size_t)(bb * Sc + s_idx) * Dc + h * DHc + d0)) = o;
    }
}

// ---------------------------------------------------------------------------
extern "C" void kernel_launch(void* const* d_in, const int* in_sizes, int n_in,
                              void* d_out, int out_size)
{
    const float* x  = (const float*)d_in[0];
    const float* wq = (const float*)d_in[1];
    const float* bq = (const float*)d_in[2];
    const float* wk = (const float*)d_in[3];
    const float* bk = (const float*)d_in[4];
    const float* wv = (const float*)d_in[5];
    const float* bv = (const float*)d_in[6];
    const float* wo = (const float*)d_in[7];
    const float* bo = (const float*)d_in[8];
    float* out = (float*)d_out;

    float *qp = nullptr, *kp = nullptr, *vp = nullptr, *cp = nullptr;
    cudaGetSymbolAddress((void**)&qp, g_q);
    cudaGetSymbolAddress((void**)&kp, g_k);
    cudaGetSymbolAddress((void**)&vp, g_v);
    cudaGetSymbolAddress((void**)&cp, g_ctx);

    const dim3 gg(Dc / 64, Mc / 64);   // (16, 128)

    // Q/K/V projections (Q scaled by 1/sqrt(Dh) = 1/8)
    gemm_bias<<<gg, 256>>>(x, wq, bq, qp, 0.125f, 1);
    gemm_bias<<<gg, 256>>>(x, wk, bk, kp, 1.0f, 1);
    gemm_bias<<<gg, 256>>>(x, wv, bv, vp, 1.0f, 1);

    // Attention
    flash_attn<<<dim3(Sc / 64, Bc * Hc), 256>>>();

    // Output projection
    gemm_bias<<<gg, 256>>>(cp, wo, bo, out, 1.0f, 0);
}

// round 2
// speedup vs baseline: 3.7730x; 3.7730x over previous
#include <cuda_runtime.h>
#include <math.h>
#include <stdint.h>

// Problem constants
constexpr int Bc = 4;
constexpr int Sc = 2048;
constexpr int Dc = 1024;
constexpr int Hc = 16;
constexpr int DHc = 64;
constexpr int Mc = Bc * Sc;    // 8192

// Scratch (device globals — no allocation allowed)
__device__ __align__(16) float g_q[(size_t)Bc * Hc * Sc * DHc];
__device__ __align__(16) float g_k[(size_t)Bc * Hc * Sc * DHc];
__device__ __align__(16) float g_v[(size_t)Bc * Hc * Sc * DHc];
__device__ __align__(16) float g_ctx[(size_t)Mc * Dc];

__device__ __forceinline__ uint32_t f2tf(float x) {
    uint32_t u;
    asm("cvt.rna.tf32.f32 %0, %1;" : "=r"(u) : "f"(x));
    return u;
}

// mma.sync m16n8k8 tf32: D += A*B, fragments per PTX ISA layout
__device__ __forceinline__ void mma8(float* c, const uint32_t* a, const uint32_t* b) {
    asm volatile(
        "mma.sync.aligned.m16n8k8.row.col.f32.tf32.tf32.f32 "
        "{%0,%1,%2,%3}, {%4,%5,%6,%7}, {%8,%9}, {%0,%1,%2,%3};\n"
        : "+f"(c[0]), "+f"(c[1]), "+f"(c[2]), "+f"(c[3])
        : "r"(a[0]), "r"(a[1]), "r"(a[2]), "r"(a[3]), "r"(b[0]), "r"(b[1]));
}

// ---------------------------------------------------------------------------
// TF32 tensor-core GEMM + bias: out = (X @ W + b) * scale
//   X [M,1024] rm, W [1024,1024] rm. Block tile 128x128, BK=16, 256 threads.
//   8 warps as 2(m) x 4(n); warp tile 64x32 (4 m-frags x 4 n-frags of m16n8k8).
//   headmode=1 writes [B,H,S,Dh]; headmode=0 writes [M,N].
// ---------------------------------------------------------------------------
__global__ __launch_bounds__(256) void gemm_tc(
    const float* __restrict__ X,
    const float* __restrict__ W,
    const float* __restrict__ bias,
    float* __restrict__ out,
    float scale, int headmode)
{
    __shared__ uint32_t As[128][20];    // [m][k], pad -> (20m+k)%32 distinct
    __shared__ uint32_t Bs[16][136];    // [k][n], pad -> (8k+n)%32 distinct

    const int tid = threadIdx.x, lane = tid & 31, wid = tid >> 5;
    const int wm = wid >> 2, wn = wid & 3;
    const int m0 = blockIdx.y * 128, n0 = blockIdx.x * 128;
    const int rq = lane >> 2, qd = lane & 3;

    float acc[4][4][4] = {};

    const int mA = tid >> 2;          // 0..63 (and +64)
    const int kqA = (tid & 3) * 4;    // 0,4,8,12
    const int kB = tid >> 5;          // 0..7 (and +8)
    const int nB = (tid & 31) * 4;    // 0..124

    for (int k0 = 0; k0 < Dc; k0 += 16) {
        const float4 a0 = *(const float4*)(X + (size_t)(m0 + mA) * Dc + k0 + kqA);
        const float4 a1 = *(const float4*)(X + (size_t)(m0 + mA + 64) * Dc + k0 + kqA);
        const float4 b0 = *(const float4*)(W + (size_t)(k0 + kB) * Dc + n0 + nB);
        const float4 b1 = *(const float4*)(W + (size_t)(k0 + kB + 8) * Dc + n0 + nB);
        __syncthreads();   // previous tile's reads done before overwrite
        As[mA][kqA + 0] = f2tf(a0.x); As[mA][kqA + 1] = f2tf(a0.y);
        As[mA][kqA + 2] = f2tf(a0.z); As[mA][kqA + 3] = f2tf(a0.w);
        As[mA + 64][kqA + 0] = f2tf(a1.x); As[mA + 64][kqA + 1] = f2tf(a1.y);
        As[mA + 64][kqA + 2] = f2tf(a1.z); As[mA + 64][kqA + 3] = f2tf(a1.w);
        Bs[kB][nB + 0] = f2tf(b0.x); Bs[kB][nB + 1] = f2tf(b0.y);
        Bs[kB][nB + 2] = f2tf(b0.z); Bs[kB][nB + 3] = f2tf(b0.w);
        Bs[kB + 8][nB + 0] = f2tf(b1.x); Bs[kB + 8][nB + 1] = f2tf(b1.y);
        Bs[kB + 8][nB + 2] = f2tf(b1.z); Bs[kB + 8][nB + 3] = f2tf(b1.w);
        __syncthreads();

        #pragma unroll
        for (int ks = 0; ks < 2; ++ks) {
            const int kb = ks * 8;
            uint32_t af[4][4];
            #pragma unroll
            for (int mf = 0; mf < 4; ++mf) {
                const int row = wm * 64 + mf * 16 + rq;
                af[mf][0] = As[row][kb + qd];
                af[mf][1] = As[row + 8][kb + qd];
                af[mf][2] = As[row][kb + qd + 4];
                af[mf][3] = As[row + 8][kb + qd + 4];
            }
            #pragma unroll
            for (int nf = 0; nf < 4; ++nf) {
                const int col = wn * 32 + nf * 8 + rq;
                uint32_t bf[2];
                bf[0] = Bs[kb + qd][col];
                bf[1] = Bs[kb + qd + 4][col];
                #pragma unroll
                for (int mf = 0; mf < 4; ++mf) mma8(acc[mf][nf], af[mf], bf);
            }
        }
    }

    // Epilogue
    #pragma unroll
    for (int nf = 0; nf < 4; ++nf) {
        const int col = n0 + wn * 32 + nf * 8 + 2 * qd;
        const float bx = bias[col], by = bias[col + 1];
        #pragma unroll
        for (int mf = 0; mf < 4; ++mf) {
            const int r = m0 + wm * 64 + mf * 16 + rq;
            float2 o0, o1;
            o0.x = (acc[mf][nf][0] + bx) * scale;
            o0.y = (acc[mf][nf][1] + by) * scale;
            o1.x = (acc[mf][nf][2] + bx) * scale;
            o1.y = (acc[mf][nf][3] + by) * scale;
            if (headmode) {
                const int h = col >> 6, d = col & 63;
                const int bb0 = r >> 11, ss0 = r & 2047;
                const int bb1 = (r + 8) >> 11, ss1 = (r + 8) & 2047;
                *(float2*)(out + (((size_t)(bb0 * Hc + h) * Sc + ss0) * DHc + d)) = o0;
                *(float2*)(out + (((size_t)(bb1 * Hc + h) * Sc + ss1) * DHc + d)) = o1;
            } else {
                *(float2*)(out + (size_t)r * Dc + col) = o0;
                *(float2*)(out + (size_t)(r + 8) * Dc + col) = o1;
            }
        }
    }
}

// ---------------------------------------------------------------------------
// TF32 tensor-core flash attention.
//   Grid (S/128, B*H), 256 threads = 8 warps; warp owns 16 query rows.
//   Key tiles of 64. Q pre-scaled by 1/sqrt(Dh) at projection.
//   S and O kept in mma accum fragments; P crosses layout via warp-private smem.
// ---------------------------------------------------------------------------
constexpr int Q_ELEMS = 128 * 68;
constexpr int K_ELEMS = 64 * 68;
constexpr int V_ELEMS = 64 * 72;
constexpr int P_ELEMS = 128 * 68;
constexpr int ATT_SMEM_BYTES = (Q_ELEMS + K_ELEMS + V_ELEMS + P_ELEMS) * 4;  // 105472

__global__ __launch_bounds__(256) void flash_tc()
{
    extern __shared__ uint32_t sm[];
    uint32_t (*Qs)[68] = (uint32_t(*)[68])sm;
    uint32_t (*Ks)[68] = (uint32_t(*)[68])(sm + Q_ELEMS);
    uint32_t (*Vs)[72] = (uint32_t(*)[72])(sm + Q_ELEMS + K_ELEMS);
    uint32_t (*Ps)[68] = (uint32_t(*)[68])(sm + Q_ELEMS + K_ELEMS + V_ELEMS);

    const int tid = threadIdx.x, lane = tid & 31, wid = tid >> 5;
    const int qt = blockIdx.x, bh = blockIdx.y;
    const float* Q = g_q + (size_t)bh * Sc * DHc;
    const float* K = g_k + (size_t)bh * Sc * DHc;
    const float* V = g_v + (size_t)bh * Sc * DHc;
    const int rq = lane >> 2, qd = lane & 3;
    const int row = wid * 16 + rq;

    // Load+convert Q tile (128 x 64)
    #pragma unroll
    for (int j = 0; j < 8; ++j) {
        const int i = tid + j * 256;
        const int r = i >> 4, c4 = (i & 15) * 4;
        const float4 q4 = *(const float4*)(Q + (size_t)(qt * 128 + r) * DHc + c4);
        Qs[r][c4 + 0] = f2tf(q4.x); Qs[r][c4 + 1] = f2tf(q4.y);
        Qs[r][c4 + 2] = f2tf(q4.z); Qs[r][c4 + 3] = f2tf(q4.w);
    }

    float accO[8][4] = {};
    float mi[2] = {-1e30f, -1e30f};
    float li[2] = {0.0f, 0.0f};

    for (int t = 0; t < Sc / 64; ++t) {
        __syncthreads();
        #pragma unroll
        for (int j = 0; j < 4; ++j) {
            const int i = tid + j * 256;
            const int r = i >> 4, c4 = (i & 15) * 4;
            const float4 k4 = *(const float4*)(K + (size_t)(t * 64 + r) * DHc + c4);
            const float4 v4 = *(const float4*)(V + (size_t)(t * 64 + r) * DHc + c4);
            Ks[r][c4 + 0] = f2tf(k4.x); Ks[r][c4 + 1] = f2tf(k4.y);
            Ks[r][c4 + 2] = f2tf(k4.z); Ks[r][c4 + 3] = f2tf(k4.w);
            Vs[r][c4 + 0] = f2tf(v4.x); Vs[r][c4 + 1] = f2tf(v4.y);
            Vs[r][c4 + 2] = f2tf(v4.z); Vs[r][c4 + 3] = f2tf(v4.w);
        }
        __syncthreads();

        // S = Q K^T  (16 rows x 64 keys per warp)
        float accS[8][4] = {};
        #pragma unroll
        for (int kk = 0; kk < 8; ++kk) {
            const int kb = kk * 8;
            uint32_t a[4];
            a[0] = Qs[row][kb + qd];
            a[1] = Qs[row + 8][kb + qd];
            a[2] = Qs[row][kb + qd + 4];
            a[3] = Qs[row + 8][kb + qd + 4];
            #pragma unroll
            for (int nf = 0; nf < 8; ++nf) {
                const int col = nf * 8 + rq;
                uint32_t b[2];
                b[0] = Ks[col][kb + qd];
                b[1] = Ks[col][kb + qd + 4];
                mma8(accS[nf], a, b);
            }
        }

        // Online softmax on fragment layout (rows rq and rq+8)
        #pragma unroll
        for (int h = 0; h < 2; ++h) {
            float mx = -1e30f;
            #pragma unroll
            for (int nf = 0; nf < 8; ++nf)
                mx = fmaxf(mx, fmaxf(accS[nf][2 * h], accS[nf][2 * h + 1]));
            mx = fmaxf(mx, __shfl_xor_sync(0xffffffffu, mx, 1));
            mx = fmaxf(mx, __shfl_xor_sync(0xffffffffu, mx, 2));
            const float mnew = fmaxf(mi[h], mx);
            const float corr = __expf(mi[h] - mnew);
            mi[h] = mnew;
            float rs = 0.0f;
            #pragma unroll
            for (int nf = 0; nf < 8; ++nf) {
                const float p0 = __expf(accS[nf][2 * h] - mnew);
                const float p1 = __expf(accS[nf][2 * h + 1] - mnew);
                rs += p0 + p1;
                Ps[row + 8 * h][nf * 8 + 2 * qd] = f2tf(p0);
                Ps[row + 8 * h][nf * 8 + 2 * qd + 1] = f2tf(p1);
            }
            rs += __shfl_xor_sync(0xffffffffu, rs, 1);
            rs += __shfl_xor_sync(0xffffffffu, rs, 2);
            li[h] = li[h] * corr + rs;
            #pragma unroll
            for (int nf = 0; nf < 8; ++nf) {
                accO[nf][2 * h] *= corr;
                accO[nf][2 * h + 1] *= corr;
            }
        }
        __syncwarp();   // Ps is warp-private: order writes before frag reads

        // O += P @ V  (16 rows x 64 dims per warp)
        #pragma unroll
        for (int kk = 0; kk < 8; ++kk) {
            const int kb = kk * 8;
            uint32_t a[4];
            a[0] = Ps[row][kb + qd];
            a[1] = Ps[row + 8][kb + qd];
            a[2] = Ps[row][kb + qd + 4];
            a[3] = Ps[row + 8][kb + qd + 4];
            #pragma unroll
            for (int nf = 0; nf < 8; ++nf) {
                const int col = nf * 8 + rq;
                uint32_t b[2];
                b[0] = Vs[kb + qd][col];
                b[1] = Vs[kb + qd + 4][col];
                mma8(accO[nf], a, b);
            }
        }
    }

    // Epilogue: normalize, write ctx [B,S,D]
    const int bb = bh >> 4, hh = bh & 15;
    #pragma unroll
    for (int h = 0; h < 2; ++h) {
        const int s_idx = qt * 128 + row + 8 * h;
        const float inv = 1.0f / li[h];
        #pragma unroll
        for (int nf = 0; nf < 8; ++nf) {
            float2 o;
            o.x = accO[nf][2 * h] * inv;
            o.y = accO[nf][2 * h + 1] * inv;
            *(float2*)(g_ctx + ((size_t)(bb * Sc + s_idx) * Dc + hh * DHc + nf * 8 + 2 * qd)) = o;
        }
    }
}

// ---------------------------------------------------------------------------
extern "C" void kernel_launch(void* const* d_in, const int* in_sizes, int n_in,
                              void* d_out, int out_size)
{
    const float* x  = (const float*)d_in[0];
    const float* wq = (const float*)d_in[1];
    const float* bq = (const float*)d_in[2];
    const float* wk = (const float*)d_in[3];
    const float* bk = (const float*)d_in[4];
    const float* wv = (const float*)d_in[5];
    const float* bv = (const float*)d_in[6];
    const float* wo = (const float*)d_in[7];
    const float* bo = (const float*)d_in[8];
    float* out = (float*)d_out;

    float *qp = nullptr, *kp = nullptr, *vp = nullptr, *cp = nullptr;
    cudaGetSymbolAddress((void**)&qp, g_q);
    cudaGetSymbolAddress((void**)&kp, g_k);
    cudaGetSymbolAddress((void**)&vp, g_v);
    cudaGetSymbolAddress((void**)&cp, g_ctx);

    cudaFuncSetAttribute(flash_tc, cudaFuncAttributeMaxDynamicSharedMemorySize,
                         ATT_SMEM_BYTES);

    const dim3 gg(Dc / 128, Mc / 128);   // (8, 64)

    gemm_tc<<<gg, 256>>>(x, wq, bq, qp, 0.125f, 1);   // Q scaled by 1/sqrt(Dh)
    gemm_tc<<<gg, 256>>>(x, wk, bk, kp, 1.0f, 1);
    gemm_tc<<<gg, 256>>>(x, wv, bv, vp, 1.0f, 1);

    flash_tc<<<dim3(Sc / 128, Bc * Hc), 256, ATT_SMEM_BYTES>>>();

    gemm_tc<<<gg, 256>>>(cp, wo, bo, out, 1.0f, 0);
}

// round 3
// speedup vs baseline: 3.8664x; 1.0248x over previous
#include <cuda_runtime.h>
#include <cuda_fp16.h>
#include <math.h>
#include <stdint.h>

// Problem constants
constexpr int Bc = 4;
constexpr int Sc = 2048;
constexpr int Dc = 1024;
constexpr int Hc = 16;
constexpr int DHc = 64;
constexpr int Mc = Bc * Sc;    // 8192

// Scratch (device globals — no allocation allowed)
__device__ __align__(16) float g_q[(size_t)Bc * Hc * Sc * DHc];
__device__ __align__(16) float g_k[(size_t)Bc * Hc * Sc * DHc];
__device__ __align__(16) float g_v[(size_t)Bc * Hc * Sc * DHc];
__device__ __align__(16) float g_ctx[(size_t)Mc * Dc];

__device__ __forceinline__ uint32_t f2tf(float x) {
    uint32_t u;
    asm("cvt.rna.tf32.f32 %0, %1;" : "=r"(u) : "f"(x));
    return u;
}

// mma.sync m16n8k8 tf32
__device__ __forceinline__ void mma8(float* c, const uint32_t* a, const uint32_t* b) {
    asm volatile(
        "mma.sync.aligned.m16n8k8.row.col.f32.tf32.tf32.f32 "
        "{%0,%1,%2,%3}, {%4,%5,%6,%7}, {%8,%9}, {%0,%1,%2,%3};\n"
        : "+f"(c[0]), "+f"(c[1]), "+f"(c[2]), "+f"(c[3])
        : "r"(a[0]), "r"(a[1]), "r"(a[2]), "r"(a[3]), "r"(b[0]), "r"(b[1]));
}

// mma.sync m16n8k16 fp16 -> fp32
__device__ __forceinline__ void mma16h(float* c, const uint32_t* a, const uint32_t* b) {
    asm volatile(
        "mma.sync.aligned.m16n8k16.row.col.f32.f16.f16.f32 "
        "{%0,%1,%2,%3}, {%4,%5,%6,%7}, {%8,%9}, {%0,%1,%2,%3};\n"
        : "+f"(c[0]), "+f"(c[1]), "+f"(c[2]), "+f"(c[3])
        : "r"(a[0]), "r"(a[1]), "r"(a[2]), "r"(a[3]), "r"(b[0]), "r"(b[1]));
}

// ---------------------------------------------------------------------------
// TF32 GEMM + bias, register-prefetch pipelined.
//   Block tile 128x128, BK=16, 256 threads, 8 warps (2m x 4n), warp 64x32.
//   A smem uses k-permuted layout: within each 8-block phys = 2(k&3)+((k>>2)&1)
//   so fragment pairs (qd, qd+4) are one LDS64.
// ---------------------------------------------------------------------------
__global__ __launch_bounds__(256, 2) void gemm_tc(
    const float* __restrict__ X,
    const float* __restrict__ W,
    const float* __restrict__ bias,
    float* __restrict__ out,
    float scale, int headmode)
{
    __shared__ uint32_t As[128][24];    // [m][perm k], pitch 24 words
    __shared__ uint32_t Bs[16][136];    // [k][n]

    const int tid = threadIdx.x, lane = tid & 31, wid = tid >> 5;
    const int wm = wid >> 2, wn = wid & 3;
    const int m0 = blockIdx.y * 128, n0 = blockIdx.x * 128;
    const int rq = lane >> 2, qd = lane & 3;

    float acc[4][4][4] = {};

    const int mA = tid >> 2;          // 0..63
    const int kqA = (tid & 3) * 4;    // 0,4,8,12
    const int kB = tid >> 5;          // 0..7
    const int nB = (tid & 31) * 4;    // 0..124
    const int pbA = (kqA & ~7) | ((kqA & 4) >> 2);

    const float* xp0 = X + (size_t)(m0 + mA) * Dc + kqA;
    const float* xp1 = xp0 + (size_t)64 * Dc;
    const float* wp0 = W + (size_t)kB * Dc + n0 + nB;
    const float* wp1 = wp0 + (size_t)8 * Dc;

    float4 a0 = *(const float4*)xp0;
    float4 a1 = *(const float4*)xp1;
    float4 b0 = *(const float4*)wp0;
    float4 b1 = *(const float4*)wp1;

    for (int k0 = 0; k0 < Dc; k0 += 16) {
        __syncthreads();
        As[mA][pbA + 0] = f2tf(a0.x); As[mA][pbA + 2] = f2tf(a0.y);
        As[mA][pbA + 4] = f2tf(a0.z); As[mA][pbA + 6] = f2tf(a0.w);
        As[mA + 64][pbA + 0] = f2tf(a1.x); As[mA + 64][pbA + 2] = f2tf(a1.y);
        As[mA + 64][pbA + 4] = f2tf(a1.z); As[mA + 64][pbA + 6] = f2tf(a1.w);
        Bs[kB][nB + 0] = f2tf(b0.x); Bs[kB][nB + 1] = f2tf(b0.y);
        Bs[kB][nB + 2] = f2tf(b0.z); Bs[kB][nB + 3] = f2tf(b0.w);
        Bs[kB + 8][nB + 0] = f2tf(b1.x); Bs[kB + 8][nB + 1] = f2tf(b1.y);
        Bs[kB + 8][nB + 2] = f2tf(b1.z); Bs[kB + 8][nB + 3] = f2tf(b1.w);
        __syncthreads();

        // Prefetch next k-tile (overlaps with mma compute below)
        if (k0 + 16 < Dc) {
            a0 = *(const float4*)(xp0 + k0 + 16);
            a1 = *(const float4*)(xp1 + k0 + 16);
            b0 = *(const float4*)(wp0 + (size_t)(k0 + 16) * Dc);
            b1 = *(const float4*)(wp1 + (size_t)(k0 + 16) * Dc);
        }

        #pragma unroll
        for (int ks = 0; ks < 2; ++ks) {
            const int kb = ks * 8 + 2 * qd;   // permuted position of (ks, qd)
            uint32_t af[4][4];
            #pragma unroll
            for (int mf = 0; mf < 4; ++mf) {
                const int row = wm * 64 + mf * 16 + rq;
                const uint2 aA = *(const uint2*)&As[row][kb];
                const uint2 aB = *(const uint2*)&As[row + 8][kb];
                af[mf][0] = aA.x; af[mf][1] = aB.x;
                af[mf][2] = aA.y; af[mf][3] = aB.y;
            }
            #pragma unroll
            for (int nf = 0; nf < 4; ++nf) {
                const int col = wn * 32 + nf * 8 + rq;
                uint32_t bf[2];
                bf[0] = Bs[ks * 8 + qd][col];
                bf[1] = Bs[ks * 8 + qd + 4][col];
                #pragma unroll
                for (int mf = 0; mf < 4; ++mf) mma8(acc[mf][nf], af[mf], bf);
            }
        }
    }

    // Epilogue
    #pragma unroll
    for (int nf = 0; nf < 4; ++nf) {
        const int col = n0 + wn * 32 + nf * 8 + 2 * qd;
        const float bx = bias[col], by = bias[col + 1];
        #pragma unroll
        for (int mf = 0; mf < 4; ++mf) {
            const int r = m0 + wm * 64 + mf * 16 + rq;
            float2 o0, o1;
            o0.x = (acc[mf][nf][0] + bx) * scale;
            o0.y = (acc[mf][nf][1] + by) * scale;
            o1.x = (acc[mf][nf][2] + bx) * scale;
            o1.y = (acc[mf][nf][3] + by) * scale;
            if (headmode) {
                const int h = col >> 6, d = col & 63;
                const int bb0 = r >> 11, ss0 = r & 2047;
                const int bb1 = (r + 8) >> 11, ss1 = (r + 8) & 2047;
                *(float2*)(out + (((size_t)(bb0 * Hc + h) * Sc + ss0) * DHc + d)) = o0;
                *(float2*)(out + (((size_t)(bb1 * Hc + h) * Sc + ss1) * DHc + d)) = o1;
            } else {
                *(float2*)(out + (size_t)r * Dc + col) = o0;
                *(float2*)(out + (size_t)(r + 8) * Dc + col) = o1;
            }
        }
    }
}

// ---------------------------------------------------------------------------
// Flash attention: tf32 QK^T + fp16 PV.
//   Grid (S/128, B*H), 256 thr = 8 warps x 16 q-rows. Key tile 64.
//   Q/K smem in k-permuted tf32 (LDS64 frags). V as key-paired half2.
//   P as fp16 in smem (warp-private rows).
// ---------------------------------------------------------------------------
constexpr int ATT_SMEM_BYTES = (128 * 72 + 64 * 72) * 4   // Qs, Ks (u32)
                             + 32 * 72 * 4                // Vp (half2)
                             + 128 * 72 * 2;              // Ps (half)  = 82944

__global__ __launch_bounds__(256, 2) void flash_tc()
{
    extern __shared__ uint32_t sm[];
    uint32_t (*Qs)[72] = (uint32_t(*)[72])sm;                    // [128][72]
    uint32_t (*Ks)[72] = (uint32_t(*)[72])(sm + 128 * 72);       // [64][72]
    __half2 (*Vp)[72]  = (__half2(*)[72])(sm + 192 * 72);        // [32][72]
    __half  (*Ps)[72]  = (__half (*)[72])(sm + 192 * 72 + 32 * 72); // [128][72]

    const int tid = threadIdx.x, lane = tid & 31, wid = tid >> 5;
    const int qt = blockIdx.x, bh = blockIdx.y;
    const float* Q = g_q + (size_t)bh * Sc * DHc;
    const float* K = g_k + (size_t)bh * Sc * DHc;
    const float* V = g_v + (size_t)bh * Sc * DHc;
    const int rq = lane >> 2, qd = lane & 3;
    const int row = wid * 16 + rq;

    // Load+convert Q tile (128 x 64) into permuted layout
    #pragma unroll
    for (int j = 0; j < 8; ++j) {
        const int i = tid + j * 256;
        const int r = i >> 4, c4 = (i & 15) * 4;
        const float4 q4 = *(const float4*)(Q + (size_t)(qt * 128 + r) * DHc + c4);
        const int pb = (c4 & ~7) | ((c4 & 4) >> 2);
        Qs[r][pb + 0] = f2tf(q4.x); Qs[r][pb + 2] = f2tf(q4.y);
        Qs[r][pb + 4] = f2tf(q4.z); Qs[r][pb + 6] = f2tf(q4.w);
    }

    float accO[8][4] = {};
    float mi[2] = {-1e30f, -1e30f};
    float li[2] = {0.0f, 0.0f};

    for (int t = 0; t < Sc / 64; ++t) {
        __syncthreads();
        #pragma unroll
        for (int j = 0; j < 4; ++j) {
            const int i = tid + j * 256;
            const int r = i >> 4, c4 = (i & 15) * 4;
            const float4 k4 = *(const float4*)(K + (size_t)(t * 64 + r) * DHc + c4);
            const float4 v4 = *(const float4*)(V + (size_t)(t * 64 + r) * DHc + c4);
            const int pb = (c4 & ~7) | ((c4 & 4) >> 2);
            Ks[r][pb + 0] = f2tf(k4.x); Ks[r][pb + 2] = f2tf(k4.y);
            Ks[r][pb + 4] = f2tf(k4.z); Ks[r][pb + 6] = f2tf(k4.w);
            __half* vh0 = (__half*)&Vp[r >> 1][c4];
            vh0[(r & 1) + 0] = __float2half_rn(v4.x);
            vh0[(r & 1) + 2] = __float2half_rn(v4.y);
            vh0[(r & 1) + 4] = __float2half_rn(v4.z);
            vh0[(r & 1) + 6] = __float2half_rn(v4.w);
        }
        __syncthreads();

        // S = Q K^T  (tf32, permuted-layout LDS64 fragment loads)
        float accS[8][4] = {};
        #pragma unroll
        for (int kk = 0; kk < 8; ++kk) {
            const int kb = kk * 8 + 2 * qd;
            const uint2 aA = *(const uint2*)&Qs[row][kb];
            const uint2 aB = *(const uint2*)&Qs[row + 8][kb];
            uint32_t a[4] = {aA.x, aB.x, aA.y, aB.y};
            #pragma unroll
            for (int nf = 0; nf < 8; ++nf) {
                const uint2 bb = *(const uint2*)&Ks[nf * 8 + rq][kb];
                uint32_t b[2] = {bb.x, bb.y};
                mma8(accS[nf], a, b);
            }
        }

        // Online softmax on fragment layout (rows rq and rq+8 of this warp)
        #pragma unroll
        for (int h = 0; h < 2; ++h) {
            float mx = -1e30f;
            #pragma unroll
            for (int nf = 0; nf < 8; ++nf)
                mx = fmaxf(mx, fmaxf(accS[nf][2 * h], accS[nf][2 * h + 1]));
            mx = fmaxf(mx, __shfl_xor_sync(0xffffffffu, mx, 1));
            mx = fmaxf(mx, __shfl_xor_sync(0xffffffffu, mx, 2));
            const float mnew = fmaxf(mi[h], mx);
            const float corr = __expf(mi[h] - mnew);
            mi[h] = mnew;
            float rs = 0.0f;
            #pragma unroll
            for (int nf = 0; nf < 8; ++nf) {
                const float p0 = __expf(accS[nf][2 * h] - mnew);
                const float p1 = __expf(accS[nf][2 * h + 1] - mnew);
                rs += p0 + p1;
                *(__half2*)&Ps[row + 8 * h][nf * 8 + 2 * qd] = __floats2half2_rn(p0, p1);
            }
            rs += __shfl_xor_sync(0xffffffffu, rs, 1);
            rs += __shfl_xor_sync(0xffffffffu, rs, 2);
            li[h] = li[h] * corr + rs;
            #pragma unroll
            for (int nf = 0; nf < 8; ++nf) {
                accO[nf][2 * h] *= corr;
                accO[nf][2 * h + 1] *= corr;
            }
        }
        __syncwarp();   // Ps rows are warp-private: order writes before frag reads

        // O += P @ V  (fp16 m16n8k16)
        #pragma unroll
        for (int kk = 0; kk < 4; ++kk) {
            const int kb = kk * 16 + 2 * qd;
            uint32_t a[4];
            a[0] = *(const uint32_t*)&Ps[row][kb];
            a[1] = *(const uint32_t*)&Ps[row + 8][kb];
            a[2] = *(const uint32_t*)&Ps[row][kb + 8];
            a[3] = *(const uint32_t*)&Ps[row + 8][kb + 8];
            #pragma unroll
            for (int nf = 0; nf < 8; ++nf) {
                const int col = nf * 8 + rq;
                uint32_t b[2];
                b[0] = *(const uint32_t*)&Vp[(kb >> 1)][col];      // keys kb, kb+1
                b[1] = *(const uint32_t*)&Vp[(kb >> 1) + 4][col];  // keys kb+8, kb+9
                mma16h(accO[nf], a, b);
            }
        }
    }

    // Epilogue: normalize, write ctx [B,S,D]
    const int bb = bh >> 4, hh = bh & 15;
    #pragma unroll
    for (int h = 0; h < 2; ++h) {
        const int s_idx = qt * 128 + row + 8 * h;
        const float inv = 1.0f / li[h];
        #pragma unroll
        for (int nf = 0; nf < 8; ++nf) {
            float2 o;
            o.x = accO[nf][2 * h] * inv;
            o.y = accO[nf][2 * h + 1] * inv;
            *(float2*)(g_ctx + ((size_t)(bb * Sc + s_idx) * Dc + hh * DHc + nf * 8 + 2 * qd)) = o;
        }
    }
}

// ---------------------------------------------------------------------------
extern "C" void kernel_launch(void* const* d_in, const int* in_sizes, int n_in,
                              void* d_out, int out_size)
{
    const float* x  = (const float*)d_in[0];
    const float* wq = (const float*)d_in[1];
    const float* bq = (const float*)d_in[2];
    const float* wk = (const float*)d_in[3];
    const float* bk = (const float*)d_in[4];
    const float* wv = (const float*)d_in[5];
    const float* bv = (const float*)d_in[6];
    const float* wo = (const float*)d_in[7];
    const float* bo = (const float*)d_in[8];
    float* out = (float*)d_out;

    float *qp = nullptr, *kp = nullptr, *vp = nullptr, *cp = nullptr;
    cudaGetSymbolAddress((void**)&qp, g_q);
    cudaGetSymbolAddress((void**)&kp, g_k);
    cudaGetSymbolAddress((void**)&vp, g_v);
    cudaGetSymbolAddress((void**)&cp, g_ctx);

    cudaFuncSetAttribute(flash_tc, cudaFuncAttributeMaxDynamicSharedMemorySize,
                         ATT_SMEM_BYTES);

    const dim3 gg(Dc / 128, Mc / 128);   // (8, 64)

    gemm_tc<<<gg, 256>>>(x, wq, bq, qp, 0.125f, 1);   // Q scaled by 1/sqrt(Dh)
    gemm_tc<<<gg, 256>>>(x, wk, bk, kp, 1.0f, 1);
    gemm_tc<<<gg, 256>>>(x, wv, bv, vp, 1.0f, 1);

    flash_tc<<<dim3(Sc / 128, Bc * Hc), 256, ATT_SMEM_BYTES>>>();

    gemm_tc<<<gg, 256>>>(cp, wo, bo, out, 1.0f, 0);
}

// round 4
// speedup vs baseline: 6.9489x; 1.7972x over previous
#include <cuda_runtime.h>
#include <cuda_fp16.h>
#include <math.h>
#include <stdint.h>

// Problem constants
constexpr int Bc = 4;
constexpr int Sc = 2048;
constexpr int Dc = 1024;
constexpr int Hc = 16;
constexpr int DHc = 64;
constexpr int Mc = Bc * Sc;    // 8192

// Scratch (device globals — fp16). q is pre-scaled by log2(e)/sqrt(Dh).
__device__ __align__(16) __half g_q[(size_t)Bc * Hc * Sc * DHc];
__device__ __align__(16) __half g_k[(size_t)Bc * Hc * Sc * DHc];
__device__ __align__(16) __half g_v[(size_t)Bc * Hc * Sc * DHc];
__device__ __align__(16) __half g_ctx[(size_t)Mc * Dc];

// ---- mma / ldmatrix primitives -------------------------------------------
__device__ __forceinline__ void mma16h(float* c, const uint32_t* a, const uint32_t* b) {
    asm volatile(
        "mma.sync.aligned.m16n8k16.row.col.f32.f16.f16.f32 "
        "{%0,%1,%2,%3}, {%4,%5,%6,%7}, {%8,%9}, {%0,%1,%2,%3};\n"
        : "+f"(c[0]), "+f"(c[1]), "+f"(c[2]), "+f"(c[3])
        : "r"(a[0]), "r"(a[1]), "r"(a[2]), "r"(a[3]), "r"(b[0]), "r"(b[1]));
}
__device__ __forceinline__ void ldsm_x4(uint32_t* r, uint32_t addr) {
    asm volatile("ldmatrix.sync.aligned.m8n8.x4.shared.b16 {%0,%1,%2,%3}, [%4];"
                 : "=r"(r[0]), "=r"(r[1]), "=r"(r[2]), "=r"(r[3]) : "r"(addr));
}
__device__ __forceinline__ void ldsm_x4t(uint32_t* r, uint32_t addr) {
    asm volatile("ldmatrix.sync.aligned.m8n8.x4.trans.shared.b16 {%0,%1,%2,%3}, [%4];"
                 : "=r"(r[0]), "=r"(r[1]), "=r"(r[2]), "=r"(r[3]) : "r"(addr));
}
__device__ __forceinline__ void ldsm_x2t(uint32_t* r, uint32_t addr) {
    asm volatile("ldmatrix.sync.aligned.m8n8.x2.trans.shared.b16 {%0,%1}, [%2];"
                 : "=r"(r[0]), "=r"(r[1]) : "r"(addr));
}
// pack(lo,hi) -> f16x2, then 2^x elementwise (one MUFU for two exps)
__device__ __forceinline__ uint32_t exp2_f16x2(float lo, float hi) {
    uint32_t u;
    asm("{\n\t.reg .b32 t;\n\t"
        "cvt.rn.f16x2.f32 t, %1, %2;\n\t"      // packs {hi=%1, lo=%2}
        "ex2.approx.f16x2 %0, t;\n\t}"
        : "=r"(u) : "f"(hi), "f"(lo));
    return u;
}

// ---------------------------------------------------------------------------
// FP16 tensor-core GEMM + bias.
//   X [M,1024] (Tin = float or half), W [1024,1024] float rm, bias float.
//   Block tile 128x128, BK=16, 256 threads, 8 warps (2m x 4n), warp 64x32.
//   HEAD: write half to [B,H,S,Dh]; else float to [M,N].
// ---------------------------------------------------------------------------
template<typename Tin, typename Tout, bool HEAD>
__global__ __launch_bounds__(256, 2) void gemm_h(
    const Tin* __restrict__ X,
    const float* __restrict__ W,
    const float* __restrict__ bias,
    Tout* __restrict__ out,
    float scale)
{
    __shared__ __align__(16) __half As[128][24];   // pitch 48B: LDSM conflict-free
    __shared__ __align__(16) __half Bs[16][136];   // pitch 272B: conflict-free

    const int tid = threadIdx.x, lane = tid & 31, wid = tid >> 5;
    const int wm = wid >> 2, wn = wid & 3;
    const int m0 = blockIdx.y * 128, n0 = blockIdx.x * 128;
    const int rq = lane >> 2, qd = lane & 3;

    float acc[4][4][4] = {};

    const int mA = tid >> 1;          // 0..127
    const int kA = (tid & 1) * 8;     // 0 or 8
    const int kB = tid >> 4;          // 0..15
    const int nB = (tid & 15) * 8;    // 0..120

    const float* wp = W + (size_t)kB * Dc + n0 + nB;

    // prefetch registers
    float4 af0, af1; uint4 ah;
    if constexpr (sizeof(Tin) == 4) {
        const float* xp = (const float*)X + (size_t)(m0 + mA) * Dc + kA;
        af0 = *(const float4*)xp;
        af1 = *(const float4*)(xp + 4);
    } else {
        ah = *(const uint4*)((const __half*)X + (size_t)(m0 + mA) * Dc + kA);
    }
    float4 bw0 = *(const float4*)wp;
    float4 bw1 = *(const float4*)(wp + 4);

    const uint32_t a_base = (uint32_t)__cvta_generic_to_shared(&As[0][0]);
    const uint32_t b_base = (uint32_t)__cvta_generic_to_shared(&Bs[0][0]);
    const uint32_t a_frag_addr = a_base + ((wm * 64 + (lane & 15)) * 24 + (lane >> 4) * 8) * 2;
    const uint32_t b_frag_addr = b_base + ((lane & 15) * 136 + wn * 32 + (lane >> 4) * 8) * 2;

    for (int k0 = 0; k0 < Dc; k0 += 16) {
        __syncthreads();
        // store A tile
        if constexpr (sizeof(Tin) == 4) {
            __half2 h0 = __floats2half2_rn(af0.x, af0.y);
            __half2 h1 = __floats2half2_rn(af0.z, af0.w);
            __half2 h2 = __floats2half2_rn(af1.x, af1.y);
            __half2 h3 = __floats2half2_rn(af1.z, af1.w);
            uint4 p = { *(uint32_t*)&h0, *(uint32_t*)&h1, *(uint32_t*)&h2, *(uint32_t*)&h3 };
            *(uint4*)&As[mA][kA] = p;
        } else {
            *(uint4*)&As[mA][kA] = ah;
        }
        // store B tile
        {
            __half2 h0 = __floats2half2_rn(bw0.x, bw0.y);
            __half2 h1 = __floats2half2_rn(bw0.z, bw0.w);
            __half2 h2 = __floats2half2_rn(bw1.x, bw1.y);
            __half2 h3 = __floats2half2_rn(bw1.z, bw1.w);
            uint4 p = { *(uint32_t*)&h0, *(uint32_t*)&h1, *(uint32_t*)&h2, *(uint32_t*)&h3 };
            *(uint4*)&Bs[kB][nB] = p;
        }
        __syncthreads();

        // prefetch next tile
        if (k0 + 16 < Dc) {
            if constexpr (sizeof(Tin) == 4) {
                const float* xp = (const float*)X + (size_t)(m0 + mA) * Dc + k0 + 16 + kA;
                af0 = *(const float4*)xp;
                af1 = *(const float4*)(xp + 4);
            } else {
                ah = *(const uint4*)((const __half*)X + (size_t)(m0 + mA) * Dc + k0 + 16 + kA);
            }
            bw0 = *(const float4*)(wp + (size_t)(k0 + 16) * Dc);
            bw1 = *(const float4*)(wp + (size_t)(k0 + 16) * Dc + 4);
        }

        // fragments + mma
        uint32_t aF[4][4];
        #pragma unroll
        for (int mf = 0; mf < 4; ++mf)
            ldsm_x4(aF[mf], a_frag_addr + mf * 16 * 24 * 2);
        #pragma unroll
        for (int ng = 0; ng < 2; ++ng) {
            uint32_t bF[4];
            ldsm_x4t(bF, b_frag_addr + ng * 16 * 2);
            #pragma unroll
            for (int s = 0; s < 2; ++s) {
                const int nf = ng * 2 + s;
                #pragma unroll
                for (int mf = 0; mf < 4; ++mf)
                    mma16h(acc[mf][nf], aF[mf], &bF[s * 2]);
            }
        }
    }

    // Epilogue
    #pragma unroll
    for (int nf = 0; nf < 4; ++nf) {
        const int col = n0 + wn * 32 + nf * 8 + 2 * qd;
        const float bx = bias[col], by = bias[col + 1];
        #pragma unroll
        for (int mf = 0; mf < 4; ++mf) {
            const int r = m0 + wm * 64 + mf * 16 + rq;
            float o00 = (acc[mf][nf][0] + bx) * scale;
            float o01 = (acc[mf][nf][1] + by) * scale;
            float o10 = (acc[mf][nf][2] + bx) * scale;
            float o11 = (acc[mf][nf][3] + by) * scale;
            if constexpr (HEAD) {
                const int h = col >> 6, d = col & 63;
                const int bb0 = r >> 11, ss0 = r & 2047;
                const int bb1 = (r + 8) >> 11, ss1 = (r + 8) & 2047;
                __half2 p0 = __floats2half2_rn(o00, o01);
                __half2 p1 = __floats2half2_rn(o10, o11);
                *(__half2*)((__half*)out + (((size_t)(bb0 * Hc + h) * Sc + ss0) * DHc + d)) = p0;
                *(__half2*)((__half*)out + (((size_t)(bb1 * Hc + h) * Sc + ss1) * DHc + d)) = p1;
            } else {
                *(float2*)((float*)out + (size_t)r * Dc + col) = make_float2(o00, o01);
                *(float2*)((float*)out + (size_t)(r + 8) * Dc + col) = make_float2(o10, o11);
            }
        }
    }
}

// ---------------------------------------------------------------------------
// FP16 flash attention, all-ldmatrix, P in registers, f16x2 exp2,
// row-sums via ones-column of V.
//   Grid (S/128, B*H), 256 thr = 8 warps x 16 q-rows. Key tile 64.
// ---------------------------------------------------------------------------
__global__ __launch_bounds__(256, 2) void flash_h()
{
    __shared__ __align__(16) __half Qs[128][72];
    __shared__ __align__(16) __half Ks[64][72];
    __shared__ __align__(16) __half Vs[64][72];   // cols 64..71: [1,0,...,0]

    const int tid = threadIdx.x, lane = tid & 31, wid = tid >> 5;
    const int qt = blockIdx.x, bh = blockIdx.y;
    const __half* Q = g_q + (size_t)bh * Sc * DHc;
    const __half* K = g_k + (size_t)bh * Sc * DHc;
    const __half* V = g_v + (size_t)bh * Sc * DHc;
    const int rq = lane >> 2, qd = lane & 3;

    const uint32_t q_base = (uint32_t)__cvta_generic_to_shared(&Qs[0][0]);
    const uint32_t k_base = (uint32_t)__cvta_generic_to_shared(&Ks[0][0]);
    const uint32_t v_base = (uint32_t)__cvta_generic_to_shared(&Vs[0][0]);

    // Fill Q tile (128 x 64 halves): 4 x uint4 per thread
    #pragma unroll
    for (int j = 0; j < 4; ++j) {
        const int i = tid + j * 256;
        const int r = i >> 3, c = (i & 7) * 8;
        *(uint4*)&Qs[r][c] = *(const uint4*)(Q + (size_t)(qt * 128 + r) * DHc + c);
    }
    // ones-column block of V (constant across tiles)
    if (tid < 64) {
        const uint4 onesv = { 0x00003C00u, 0u, 0u, 0u };   // half 1.0 at col 64
        *(uint4*)&Vs[tid][64] = onesv;
    }
    __syncthreads();

    // Q fragments held in registers for the whole loop
    uint32_t aQ[4][4];
    {
        const uint32_t qa = q_base + ((wid * 16 + (lane & 15)) * 72 + (lane >> 4) * 8) * 2;
        #pragma unroll
        for (int kk = 0; kk < 4; ++kk)
            ldsm_x4(aQ[kk], qa + kk * 16 * 2);
    }

    float accO[8][4] = {};
    float accO8[4] = {};            // ones-column accumulator -> row sums
    float mi[2] = {-1e30f, -1e30f};

    const uint32_t k_frag = k_base + (((lane >> 4) * 8 + (lane & 7)) * 72 + ((lane >> 3) & 1) * 8) * 2;
    const uint32_t v_frag = v_base + ((lane & 15) * 72 + (lane >> 4) * 8) * 2;
    const uint32_t v1_frag = v_base + ((lane & 15) * 72 + 64) * 2;

    for (int t = 0; t < Sc / 64; ++t) {
        __syncthreads();
        #pragma unroll
        for (int j = 0; j < 2; ++j) {
            const int i = tid + j * 256;
            const int r = i >> 3, c = (i & 7) * 8;
            *(uint4*)&Ks[r][c] = *(const uint4*)(K + (size_t)(t * 64 + r) * DHc + c);
            *(uint4*)&Vs[r][c] = *(const uint4*)(V + (size_t)(t * 64 + r) * DHc + c);
        }
        __syncthreads();

        // S = Q K^T  (scores already in log2 units: Q pre-scaled by log2e/8)
        float accS[8][4] = {};
        #pragma unroll
        for (int kk = 0; kk < 4; ++kk) {
            #pragma unroll
            for (int ng = 0; ng < 4; ++ng) {
                uint32_t bK[4];
                ldsm_x4(bK, k_frag + (ng * 16 * 72 + kk * 16) * 2);
                mma16h(accS[2 * ng],     aQ[kk], &bK[0]);
                mma16h(accS[2 * ng + 1], aQ[kk], &bK[2]);
            }
        }

        // Online softmax -> P packed directly into mma A-fragments (aP)
        uint32_t aP[4][4];
        #pragma unroll
        for (int h = 0; h < 2; ++h) {
            float mx = -1e30f;
            #pragma unroll
            for (int nf = 0; nf < 8; ++nf)
                mx = fmaxf(mx, fmaxf(accS[nf][2 * h], accS[nf][2 * h + 1]));
            mx = fmaxf(mx, __shfl_xor_sync(0xffffffffu, mx, 1));
            mx = fmaxf(mx, __shfl_xor_sync(0xffffffffu, mx, 2));
            const float mnew = fmaxf(mi[h], mx);
            const float corr = exp2f(mi[h] - mnew);
            mi[h] = mnew;
            #pragma unroll
            for (int nf = 0; nf < 8; ++nf) {
                const uint32_t ph = exp2_f16x2(accS[nf][2 * h] - mnew,
                                               accS[nf][2 * h + 1] - mnew);
                aP[nf >> 1][((nf & 1) << 1) | h] = ph;
            }
            #pragma unroll
            for (int nf = 0; nf < 8; ++nf) {
                accO[nf][2 * h] *= corr;
                accO[nf][2 * h + 1] *= corr;
            }
            accO8[2 * h] *= corr;
            accO8[2 * h + 1] *= corr;
        }

        // O += P @ V   (+ ones-column -> row sums into accO8)
        #pragma unroll
        for (int kk = 0; kk < 4; ++kk) {
            #pragma unroll
            for (int dg = 0; dg < 4; ++dg) {
                uint32_t bV[4];
                ldsm_x4t(bV, v_frag + (kk * 16 * 72 + dg * 16) * 2);
                mma16h(accO[2 * dg],     aP[kk], &bV[0]);
                mma16h(accO[2 * dg + 1], aP[kk], &bV[2]);
            }
            uint32_t b1[2];
            ldsm_x2t(b1, v1_frag + kk * 16 * 72 * 2);
            mma16h(accO8, aP[kk], b1);
        }
    }

    // Epilogue: li lives in accO8 (col 64 -> qd==0 threads); broadcast in quad
    const float li0 = __shfl_sync(0xffffffffu, accO8[0], lane & ~3);
    const float li1 = __shfl_sync(0xffffffffu, accO8[2], lane & ~3);
    const float inv0 = 1.0f / li0;
    const float inv1 = 1.0f / li1;

    const int bb = bh >> 4, hh = bh & 15;
    const int row = wid * 16 + rq;
    #pragma unroll
    for (int h = 0; h < 2; ++h) {
        const int s_idx = qt * 128 + row + 8 * h;
        const float inv = h ? inv1 : inv0;
        #pragma unroll
        for (int nf = 0; nf < 8; ++nf) {
            __half2 o = __floats2half2_rn(accO[nf][2 * h] * inv,
                                          accO[nf][2 * h + 1] * inv);
            *(__half2*)(g_ctx + ((size_t)(bb * Sc + s_idx) * Dc + hh * DHc + nf * 8 + 2 * qd)) = o;
        }
    }
}

// ---------------------------------------------------------------------------
extern "C" void kernel_launch(void* const* d_in, const int* in_sizes, int n_in,
                              void* d_out, int out_size)
{
    const float* x  = (const float*)d_in[0];
    const float* wq = (const float*)d_in[1];
    const float* bq = (const float*)d_in[2];
    const float* wk = (const float*)d_in[3];
    const float* bk = (const float*)d_in[4];
    const float* wv = (const float*)d_in[5];
    const float* bv = (const float*)d_in[6];
    const float* wo = (const float*)d_in[7];
    const float* bo = (const float*)d_in[8];
    float* out = (float*)d_out;

    __half *qp = nullptr, *kp = nullptr, *vp = nullptr, *cp = nullptr;
    cudaGetSymbolAddress((void**)&qp, g_q);
    cudaGetSymbolAddress((void**)&kp, g_k);
    cudaGetSymbolAddress((void**)&vp, g_v);
    cudaGetSymbolAddress((void**)&cp, g_ctx);

    const dim3 gg(Dc / 128, Mc / 128);   // (8, 64)
    const float qscale = 1.4426950408889634f / 8.0f;   // log2(e)/sqrt(Dh)

    gemm_h<float, __half, true><<<gg, 256>>>(x, wq, bq, qp, qscale);
    gemm_h<float, __half, true><<<gg, 256>>>(x, wk, bk, kp, 1.0f);
    gemm_h<float, __half, true><<<gg, 256>>>(x, wv, bv, vp, 1.0f);

    flash_h<<<dim3(Sc / 128, Bc * Hc), 256>>>();

    gemm_h<__half, float, false><<<gg, 256>>>(cp, wo, bo, out, 1.0f);
}

// round 5
// speedup vs baseline: 9.4971x; 1.3667x over previous
#include <cuda_runtime.h>
#include <cuda_fp16.h>
#include <math.h>
#include <stdint.h>

// Problem constants
constexpr int Bc = 4;
constexpr int Sc = 2048;
constexpr int Dc = 1024;
constexpr int Hc = 16;
constexpr int DHc = 64;
constexpr int Mc = Bc * Sc;    // 8192

// Scratch (device globals — no allocation allowed)
__device__ __align__(16) __half g_q[(size_t)Bc * Hc * Sc * DHc];
__device__ __align__(16) __half g_k[(size_t)Bc * Hc * Sc * DHc];
__device__ __align__(16) __half g_v[(size_t)Bc * Hc * Sc * DHc];
__device__ __align__(16) __half g_ctx[(size_t)Mc * Dc];
__device__ __align__(16) __half g_xh[(size_t)Mc * Dc];          // x in fp16
__device__ __align__(16) __half g_wcat[(size_t)Dc * 3 * Dc];    // [k][3072] = Wq|Wk|Wv
__device__ __align__(16) __half g_woh[(size_t)Dc * Dc];         // Wo fp16

// ---- primitives ------------------------------------------------------------
__device__ __forceinline__ void mma16h(float* c, const uint32_t* a, const uint32_t* b) {
    asm volatile(
        "mma.sync.aligned.m16n8k16.row.col.f32.f16.f16.f32 "
        "{%0,%1,%2,%3}, {%4,%5,%6,%7}, {%8,%9}, {%0,%1,%2,%3};\n"
        : "+f"(c[0]), "+f"(c[1]), "+f"(c[2]), "+f"(c[3])
        : "r"(a[0]), "r"(a[1]), "r"(a[2]), "r"(a[3]), "r"(b[0]), "r"(b[1]));
}
__device__ __forceinline__ void ldsm_x4(uint32_t* r, uint32_t addr) {
    asm volatile("ldmatrix.sync.aligned.m8n8.x4.shared.b16 {%0,%1,%2,%3}, [%4];"
                 : "=r"(r[0]), "=r"(r[1]), "=r"(r[2]), "=r"(r[3]) : "r"(addr));
}
__device__ __forceinline__ void ldsm_x4t(uint32_t* r, uint32_t addr) {
    asm volatile("ldmatrix.sync.aligned.m8n8.x4.trans.shared.b16 {%0,%1,%2,%3}, [%4];"
                 : "=r"(r[0]), "=r"(r[1]), "=r"(r[2]), "=r"(r[3]) : "r"(addr));
}
__device__ __forceinline__ void ldsm_x2t(uint32_t* r, uint32_t addr) {
    asm volatile("ldmatrix.sync.aligned.m8n8.x2.trans.shared.b16 {%0,%1}, [%2];"
                 : "=r"(r[0]), "=r"(r[1]) : "r"(addr));
}
__device__ __forceinline__ uint32_t exp2_f16x2(float lo, float hi) {
    uint32_t u;
    asm("{\n\t.reg .b32 t;\n\t"
        "cvt.rn.f16x2.f32 t, %1, %2;\n\t"
        "ex2.approx.f16x2 %0, t;\n\t}"
        : "=r"(u) : "f"(hi), "f"(lo));
    return u;
}
__device__ __forceinline__ void cp16(uint32_t saddr, const void* g) {
    asm volatile("cp.async.cg.shared.global [%0], [%1], 16;" :: "r"(saddr), "l"(g));
}
__device__ __forceinline__ void cp_commit() { asm volatile("cp.async.commit_group;" ::: "memory"); }
__device__ __forceinline__ void cp_wait1()  { asm volatile("cp.async.wait_group 1;" ::: "memory"); }
__device__ __forceinline__ void cp_wait0()  { asm volatile("cp.async.wait_group 0;" ::: "memory"); }

// ---------------------------------------------------------------------------
// fp32 -> fp16 conversion pre-pass kernels
// ---------------------------------------------------------------------------
__global__ __launch_bounds__(256) void cvt_x(const float* __restrict__ x) {
    const size_t i = ((size_t)blockIdx.x * 256 + threadIdx.x) * 8;
    const float4 f0 = *(const float4*)(x + i);
    const float4 f1 = *(const float4*)(x + i + 4);
    __half2 h0 = __floats2half2_rn(f0.x, f0.y), h1 = __floats2half2_rn(f0.z, f0.w);
    __half2 h2 = __floats2half2_rn(f1.x, f1.y), h3 = __floats2half2_rn(f1.z, f1.w);
    uint4 p = { *(uint32_t*)&h0, *(uint32_t*)&h1, *(uint32_t*)&h2, *(uint32_t*)&h3 };
    *(uint4*)(g_xh + i) = p;
}
__global__ __launch_bounds__(256) void cvt_w(const float* __restrict__ wq,
                                             const float* __restrict__ wk,
                                             const float* __restrict__ wv,
                                             const float* __restrict__ wo) {
    const size_t i = ((size_t)blockIdx.x * 256 + threadIdx.x) * 4;
    const int k = (int)(i >> 10), n = (int)(i & 1023);
    const float4 q4 = *(const float4*)(wq + i);
    const float4 k4 = *(const float4*)(wk + i);
    const float4 v4 = *(const float4*)(wv + i);
    const float4 o4 = *(const float4*)(wo + i);
    __half2 a, b;
    a = __floats2half2_rn(q4.x, q4.y); b = __floats2half2_rn(q4.z, q4.w);
    { uint2 p = { *(uint32_t*)&a, *(uint32_t*)&b }; *(uint2*)(g_wcat + (size_t)k * 3072 + n) = p; }
    a = __floats2half2_rn(k4.x, k4.y); b = __floats2half2_rn(k4.z, k4.w);
    { uint2 p = { *(uint32_t*)&a, *(uint32_t*)&b }; *(uint2*)(g_wcat + (size_t)k * 3072 + 1024 + n) = p; }
    a = __floats2half2_rn(v4.x, v4.y); b = __floats2half2_rn(v4.z, v4.w);
    { uint2 p = { *(uint32_t*)&a, *(uint32_t*)&b }; *(uint2*)(g_wcat + (size_t)k * 3072 + 2048 + n) = p; }
    a = __floats2half2_rn(o4.x, o4.y); b = __floats2half2_rn(o4.z, o4.w);
    { uint2 p = { *(uint32_t*)&a, *(uint32_t*)&b }; *(uint2*)(g_woh + i) = p; }
}

// ---------------------------------------------------------------------------
// FP16 GEMM, cp.async 2-stage double buffer, BK=32.
//   Block tile 128x128, 256 threads, 8 warps (2m x 4n), warp 64x32.
//   QKV=true:  A=g_xh, W=g_wcat (ld 3072), out -> g_q/g_k/g_v head-major fp16,
//              wsel = blockIdx.x>>3 picks bias/scale/output.
//   QKV=false: A=g_ctx, W=g_woh (ld 1024), out -> float [M,1024] (d_out).
// ---------------------------------------------------------------------------
template<bool QKV>
__global__ __launch_bounds__(256, 2) void gemm_cp(
    const float* __restrict__ bias0,
    const float* __restrict__ bias1,
    const float* __restrict__ bias2,
    float* __restrict__ outF,
    float qscale)
{
    __shared__ __align__(16) __half As[2][128][40];   // pitch 80B (5x16B)
    __shared__ __align__(16) __half Bs[2][32][136];   // pitch 272B (17x16B)
    constexpr uint32_t A_STG = 128 * 40 * 2;          // 10240
    constexpr uint32_t B_STG = 32 * 136 * 2;          // 8704
    constexpr int LDW = QKV ? 3072 : 1024;

    const __half* A = QKV ? g_xh : g_ctx;
    const __half* W = QKV ? g_wcat : g_woh;

    const int tid = threadIdx.x, lane = tid & 31, wid = tid >> 5;
    const int wm = wid >> 2, wn = wid & 3;
    const int m0 = blockIdx.y * 128;
    const int n0 = blockIdx.x * 128;
    const int rq = lane >> 2, qd = lane & 3;

    const uint32_t a_base = (uint32_t)__cvta_generic_to_shared(&As[0][0][0]);
    const uint32_t b_base = (uint32_t)__cvta_generic_to_shared(&Bs[0][0][0]);

    // cp.async source/dest for this thread
    const int rA = tid >> 2, cA = (tid & 3) * 8;          // A: 2 chunks (rA, rA+64)
    const int rB = tid >> 4, cB = (tid & 15) * 8;         // B: 2 chunks (rB, rB+16)
    const uint32_t aDst0 = a_base + (rA * 40 + cA) * 2;
    const uint32_t aDst1 = a_base + ((rA + 64) * 40 + cA) * 2;
    const uint32_t bDst0 = b_base + (rB * 136 + cB) * 2;
    const uint32_t bDst1 = b_base + ((rB + 16) * 136 + cB) * 2;
    const __half* aSrc0 = A + (size_t)(m0 + rA) * Dc + cA;
    const __half* aSrc1 = A + (size_t)(m0 + rA + 64) * Dc + cA;
    const __half* bSrc0 = W + (size_t)rB * LDW + n0 + cB;
    const __half* bSrc1 = W + (size_t)(rB + 16) * LDW + n0 + cB;

    // fragment base addresses
    const uint32_t a_frag = a_base + ((wm * 64 + (lane & 15)) * 40 + (lane >> 4) * 8) * 2;
    const uint32_t b_frag = b_base + ((lane & 15) * 136 + wn * 32 + (lane >> 4) * 8) * 2;

    float acc[4][4][4] = {};

    // preload stage 0
    cp16(aDst0, aSrc0); cp16(aDst1, aSrc1);
    cp16(bDst0, bSrc0); cp16(bDst1, bSrc1);
    cp_commit();

    for (int it = 0; it < Dc / 32; ++it) {
        const int s = it & 1;
        if (it + 1 < Dc / 32) {
            const int kn = (it + 1) * 32;
            const uint32_t so = (uint32_t)((it + 1) & 1);
            cp16(aDst0 + so * A_STG, aSrc0 + kn);
            cp16(aDst1 + so * A_STG, aSrc1 + kn);
            cp16(bDst0 + so * B_STG, bSrc0 + (size_t)kn * LDW);
            cp16(bDst1 + so * B_STG, bSrc1 + (size_t)kn * LDW);
            cp_commit();
            cp_wait1();
        } else {
            cp_wait0();
        }
        __syncthreads();

        const uint32_t aS = a_frag + s * A_STG;
        const uint32_t bS = b_frag + s * B_STG;
        #pragma unroll
        for (int kk = 0; kk < 2; ++kk) {
            uint32_t aF[4][4];
            #pragma unroll
            for (int mf = 0; mf < 4; ++mf)
                ldsm_x4(aF[mf], aS + (mf * 16 * 40 + kk * 16) * 2);
            #pragma unroll
            for (int ng = 0; ng < 2; ++ng) {
                uint32_t bF[4];
                ldsm_x4t(bF, bS + (kk * 16 * 136 + ng * 16) * 2);
                #pragma unroll
                for (int s2 = 0; s2 < 2; ++s2) {
                    const int nf = ng * 2 + s2;
                    #pragma unroll
                    for (int mf = 0; mf < 4; ++mf)
                        mma16h(acc[mf][nf], aF[mf], &bF[s2 * 2]);
                }
            }
        }
        __syncthreads();
    }

    // Epilogue
    if constexpr (QKV) {
        const int wsel = blockIdx.x >> 3;
        const int nl0 = (blockIdx.x & 7) * 128;
        __half* outp = wsel == 0 ? g_q : wsel == 1 ? g_k : g_v;
        const float* bp = wsel == 0 ? bias0 : wsel == 1 ? bias1 : bias2;
        const float scale = wsel == 0 ? qscale : 1.0f;
        #pragma unroll
        for (int nf = 0; nf < 4; ++nf) {
            const int ncol = nl0 + wn * 32 + nf * 8 + 2 * qd;
            const float bx = bp[ncol], by = bp[ncol + 1];
            const int h = ncol >> 6, d = ncol & 63;
            #pragma unroll
            for (int mf = 0; mf < 4; ++mf) {
                const int r = m0 + wm * 64 + mf * 16 + rq;
                __half2 p0 = __floats2half2_rn((acc[mf][nf][0] + bx) * scale,
                                               (acc[mf][nf][1] + by) * scale);
                __half2 p1 = __floats2half2_rn((acc[mf][nf][2] + bx) * scale,
                                               (acc[mf][nf][3] + by) * scale);
                const int bb0 = r >> 11, ss0 = r & 2047;
                const int bb1 = (r + 8) >> 11, ss1 = (r + 8) & 2047;
                *(__half2*)(outp + (((size_t)(bb0 * Hc + h) * Sc + ss0) * DHc + d)) = p0;
                *(__half2*)(outp + (((size_t)(bb1 * Hc + h) * Sc + ss1) * DHc + d)) = p1;
            }
        }
    } else {
        #pragma unroll
        for (int nf = 0; nf < 4; ++nf) {
            const int col = n0 + wn * 32 + nf * 8 + 2 * qd;
            const float bx = bias0[col], by = bias0[col + 1];
            #pragma unroll
            for (int mf = 0; mf < 4; ++mf) {
                const int r = m0 + wm * 64 + mf * 16 + rq;
                *(float2*)(outF + (size_t)r * Dc + col) =
                    make_float2(acc[mf][nf][0] + bx, acc[mf][nf][1] + by);
                *(float2*)(outF + (size_t)(r + 8) * Dc + col) =
                    make_float2(acc[mf][nf][2] + bx, acc[mf][nf][3] + by);
            }
        }
    }
}

// ---------------------------------------------------------------------------
// FP16 flash attention, cp.async double-buffered K/V, P in registers,
// f16x2 exp2, row sums via ones-column of V.
//   Grid (S/128, B*H), 256 thr = 8 warps x 16 q-rows. Key tile 64.
// ---------------------------------------------------------------------------
constexpr int F_Q_OFF = 0;                       // halves
constexpr int F_K_OFF = 128 * 72;                // 2 stages of 64x72
constexpr int F_V_OFF = F_K_OFF + 2 * 64 * 72;
constexpr int F_STG   = 64 * 72;                 // halves per stage
constexpr int FLASH_SMEM = (F_V_OFF + 2 * 64 * 72) * 2;   // 55296 bytes

__global__ __launch_bounds__(256, 2) void flash_h()
{
    extern __shared__ __half dsm[];
    const int tid = threadIdx.x, lane = tid & 31, wid = tid >> 5;
    const int qt = blockIdx.x, bh = blockIdx.y;
    const __half* Q = g_q + (size_t)bh * Sc * DHc;
    const __half* K = g_k + (size_t)bh * Sc * DHc;
    const __half* V = g_v + (size_t)bh * Sc * DHc;
    const int rq = lane >> 2, qd = lane & 3;

    const uint32_t base = (uint32_t)__cvta_generic_to_shared(dsm);
    const uint32_t k_base = base + F_K_OFF * 2;
    const uint32_t v_base = base + F_V_OFF * 2;

    // Fill Q tile (128 x 64 halves)
    __half (*Qs)[72] = (__half(*)[72])dsm;
    #pragma unroll
    for (int j = 0; j < 4; ++j) {
        const int i = tid + j * 256;
        const int r = i >> 3, c = (i & 7) * 8;
        *(uint4*)&Qs[r][c] = *(const uint4*)(Q + (size_t)(qt * 128 + r) * DHc + c);
    }
    // ones-column blocks of V (both stages; cp.async never touches cols 64-71)
    if (tid < 128) {
        __half* Vb = dsm + F_V_OFF;
        const uint4 onesv = { 0x00003C00u, 0u, 0u, 0u };
        *(uint4*)&Vb[(size_t)tid * 72 + 64] = onesv;
    }

    // cp.async K/V issue (2 x 16B per array per thread)
    const int rKV = tid >> 3, cKV = (tid & 7) * 8;    // rows rKV, rKV+32
    const uint32_t kD0 = k_base + (rKV * 72 + cKV) * 2;
    const uint32_t kD1 = k_base + ((rKV + 32) * 72 + cKV) * 2;
    const uint32_t vD0 = v_base + (rKV * 72 + cKV) * 2;
    const uint32_t vD1 = v_base + ((rKV + 32) * 72 + cKV) * 2;

    // preload t=0
    cp16(kD0, K + (size_t)rKV * DHc + cKV);
    cp16(kD1, K + (size_t)(rKV + 32) * DHc + cKV);
    cp16(vD0, V + (size_t)rKV * DHc + cKV);
    cp16(vD1, V + (size_t)(rKV + 32) * DHc + cKV);
    cp_commit();
    __syncthreads();

    // Q fragments held in registers for the whole loop
    uint32_t aQ[4][4];
    {
        const uint32_t qa = base + ((wid * 16 + (lane & 15)) * 72 + (lane >> 4) * 8) * 2;
        #pragma unroll
        for (int kk = 0; kk < 4; ++kk)
            ldsm_x4(aQ[kk], qa + kk * 16 * 2);
    }

    float accO[8][4] = {};
    float accO8[4] = {};
    float mi[2] = {-1e30f, -1e30f};

    const uint32_t k_frag = k_base + (((lane >> 4) * 8 + (lane & 7)) * 72 + ((lane >> 3) & 1) * 8) * 2;
    const uint32_t v_frag = v_base + ((lane & 15) * 72 + (lane >> 4) * 8) * 2;
    const uint32_t v1_frag = v_base + ((lane & 15) * 72 + 64) * 2;

    for (int t = 0; t < Sc / 64; ++t) {
        const uint32_t so = (uint32_t)(t & 1) * F_STG * 2;
        if (t + 1 < Sc / 64) {
            const uint32_t sn = (uint32_t)((t + 1) & 1) * F_STG * 2;
            const size_t go = (size_t)(t + 1) * 64 * DHc;
            cp16(kD0 + sn, K + go + (size_t)rKV * DHc + cKV);
            cp16(kD1 + sn, K + go + (size_t)(rKV + 32) * DHc + cKV);
            cp16(vD0 + sn, V + go + (size_t)rKV * DHc + cKV);
            cp16(vD1 + sn, V + go + (size_t)(rKV + 32) * DHc + cKV);
            cp_commit();
            cp_wait1();
        } else {
            cp_wait0();
        }
        __syncthreads();

        // S = Q K^T  (log2-unit scores: Q pre-scaled by log2e/8)
        float accS[8][4] = {};
        #pragma unroll
        for (int kk = 0; kk < 4; ++kk) {
            #pragma unroll
            for (int ng = 0; ng < 4; ++ng) {
                uint32_t bK[4];
                ldsm_x4(bK, k_frag + so + (ng * 16 * 72 + kk * 16) * 2);
                mma16h(accS[2 * ng],     aQ[kk], &bK[0]);
                mma16h(accS[2 * ng + 1], aQ[kk], &bK[2]);
            }
        }

        // Online softmax -> P packed directly into mma A-fragments
        uint32_t aP[4][4];
        #pragma unroll
        for (int h = 0; h < 2; ++h) {
            float mx = -1e30f;
            #pragma unroll
            for (int nf = 0; nf < 8; ++nf)
                mx = fmaxf(mx, fmaxf(accS[nf][2 * h], accS[nf][2 * h + 1]));
            mx = fmaxf(mx, __shfl_xor_sync(0xffffffffu, mx, 1));
            mx = fmaxf(mx, __shfl_xor_sync(0xffffffffu, mx, 2));
            const float mnew = fmaxf(mi[h], mx);
            const float corr = exp2f(mi[h] - mnew);
            mi[h] = mnew;
            #pragma unroll
            for (int nf = 0; nf < 8; ++nf) {
                const uint32_t ph = exp2_f16x2(accS[nf][2 * h] - mnew,
                                               accS[nf][2 * h + 1] - mnew);
                aP[nf >> 1][((nf & 1) << 1) | h] = ph;
            }
            #pragma unroll
            for (int nf = 0; nf < 8; ++nf) {
                accO[nf][2 * h] *= corr;
                accO[nf][2 * h + 1] *= corr;
            }
            accO8[2 * h] *= corr;
            accO8[2 * h + 1] *= corr;
        }

        // O += P @ V  (+ ones-column -> row sums)
        #pragma unroll
        for (int kk = 0; kk < 4; ++kk) {
            #pragma unroll
            for (int dg = 0; dg < 4; ++dg) {
                uint32_t bV[4];
                ldsm_x4t(bV, v_frag + so + (kk * 16 * 72 + dg * 16) * 2);
                mma16h(accO[2 * dg],     aP[kk], &bV[0]);
                mma16h(accO[2 * dg + 1], aP[kk], &bV[2]);
            }
            uint32_t b1[2];
            ldsm_x2t(b1, v1_frag + so + kk * 16 * 72 * 2);
            mma16h(accO8, aP[kk], b1);
        }
        __syncthreads();
    }

    // Epilogue
    const float li0 = __shfl_sync(0xffffffffu, accO8[0], lane & ~3);
    const float li1 = __shfl_sync(0xffffffffu, accO8[2], lane & ~3);
    const float inv0 = 1.0f / li0;
    const float inv1 = 1.0f / li1;

    const int bb = bh >> 4, hh = bh & 15;
    const int row = wid * 16 + rq;
    #pragma unroll
    for (int h = 0; h < 2; ++h) {
        const int s_idx = qt * 128 + row + 8 * h;
        const float inv = h ? inv1 : inv0;
        #pragma unroll
        for (int nf = 0; nf < 8; ++nf) {
            __half2 o = __floats2half2_rn(accO[nf][2 * h] * inv,
                                          accO[nf][2 * h + 1] * inv);
            *(__half2*)(g_ctx + ((size_t)(bb * Sc + s_idx) * Dc + hh * DHc + nf * 8 + 2 * qd)) = o;
        }
    }
}

// ---------------------------------------------------------------------------
extern "C" void kernel_launch(void* const* d_in, const int* in_sizes, int n_in,
                              void* d_out, int out_size)
{
    const float* x  = (const float*)d_in[0];
    const float* wq = (const float*)d_in[1];
    const float* bq = (const float*)d_in[2];
    const float* wk = (const float*)d_in[3];
    const float* bk = (const float*)d_in[4];
    const float* wv = (const float*)d_in[5];
    const float* bv = (const float*)d_in[6];
    const float* wo = (const float*)d_in[7];
    const float* bo = (const float*)d_in[8];
    float* out = (float*)d_out;

    static bool attr_set = false;
    if (!attr_set) {
        cudaFuncSetAttribute(flash_h, cudaFuncAttributeMaxDynamicSharedMemorySize,
                             FLASH_SMEM);
        attr_set = true;
    }

    const float qscale = 1.4426950408889634f / 8.0f;   // log2(e)/sqrt(Dh)

    // fp32 -> fp16 conversion pre-pass
    cvt_x<<<(int)((size_t)Mc * Dc / (256 * 8)), 256>>>(x);
    cvt_w<<<(int)((size_t)Dc * Dc / (256 * 4)), 256>>>(wq, wk, wv, wo);

    // Fused QKV projection (N = 3072)
    gemm_cp<true><<<dim3(3 * Dc / 128, Mc / 128), 256>>>(bq, bk, bv, nullptr, qscale);

    // Attention
    flash_h<<<dim3(Sc / 128, Bc * Hc), 256, FLASH_SMEM>>>();

    // Output projection
    gemm_cp<false><<<dim3(Dc / 128, Mc / 128), 256>>>(bo, nullptr, nullptr, out, 1.0f);
}